// round 17
// baseline (speedup 1.0000x reference)
#include <cuda_runtime.h>
#include <cuda_bf16.h>
#include <math.h>
#include <stdint.h>

// Problem constants
#define B_    4
#define T_    2048
#define C_    2048
#define H_    16
#define D_    128
#define NQKV_ 6144
#define MROWS 8192

// ---------------------------------------------------------------------------
// Scratch (device globals — no allocations allowed)
// ---------------------------------------------------------------------------
__device__ __align__(256) float g_Q[(size_t)B_ * H_ * T_ * D_];
__device__ __align__(256) float g_K[(size_t)B_ * H_ * T_ * D_];
__device__ __align__(256) float g_V[(size_t)B_ * H_ * T_ * D_];
__device__ __align__(256) float g_cos[T_ * 64];
__device__ __align__(256) float g_sin[T_ * 64];
// pre-split bf16 hi/lo operands ([row][k] K-major, K = 2048)
__device__ __align__(256) __nv_bfloat16 g_xh[(size_t)MROWS * C_];
__device__ __align__(256) __nv_bfloat16 g_xl[(size_t)MROWS * C_];
__device__ __align__(256) __nv_bfloat16 g_wah[(size_t)NQKV_ * C_];
__device__ __align__(256) __nv_bfloat16 g_wal[(size_t)NQKV_ * C_];
__device__ __align__(256) __nv_bfloat16 g_wph[(size_t)C_ * C_];
__device__ __align__(256) __nv_bfloat16 g_wpl[(size_t)C_ * C_];
__device__ __align__(256) __nv_bfloat16 g_Yh[(size_t)MROWS * C_];
__device__ __align__(256) __nv_bfloat16 g_Yl[(size_t)MROWS * C_];

// ---------------------------------------------------------------------------
// helpers
// ---------------------------------------------------------------------------
__device__ __forceinline__ uint32_t smem_u32(const void* p) {
    uint32_t a;
    asm("{ .reg .u64 t; cvta.to.shared.u64 t, %1; cvt.u32.u64 %0, t; }" : "=r"(a) : "l"(p));
    return a;
}

#define CP_ASYNC16(dst, src) \
    asm volatile("cp.async.cg.shared.global [%0], [%1], 16;" :: "r"(dst), "l"(src) : "memory")
#define CP_COMMIT() asm volatile("cp.async.commit_group;" ::: "memory")
#define CP_WAIT1()  asm volatile("cp.async.wait_group 1;" ::: "memory")
#define CP_WAIT0()  asm volatile("cp.async.wait_group 0;" ::: "memory")

__device__ __forceinline__ void split_pair(float x0, float x1, unsigned& h, unsigned& l) {
    __nv_bfloat16 h0 = __float2bfloat16_rn(x0);
    __nv_bfloat16 h1 = __float2bfloat16_rn(x1);
    __nv_bfloat16 l0 = __float2bfloat16_rn(x0 - __bfloat162float(h0));
    __nv_bfloat16 l1 = __float2bfloat16_rn(x1 - __bfloat162float(h1));
    __nv_bfloat162 hh = __halves2bfloat162(h0, h1);
    __nv_bfloat162 ll = __halves2bfloat162(l0, l1);
    h = *reinterpret_cast<unsigned*>(&hh);
    l = *reinterpret_cast<unsigned*>(&ll);
}

__device__ __forceinline__ void mma_bf16(float c[4], const unsigned a[4], const unsigned b[2]) {
    asm volatile(
        "mma.sync.aligned.m16n8k16.row.col.f32.bf16.bf16.f32 "
        "{%0,%1,%2,%3}, {%4,%5,%6,%7}, {%8,%9}, {%0,%1,%2,%3};"
        : "+f"(c[0]), "+f"(c[1]), "+f"(c[2]), "+f"(c[3])
        : "r"(a[0]), "r"(a[1]), "r"(a[2]), "r"(a[3]), "r"(b[0]), "r"(b[1]));
}
__device__ __forceinline__ void mma_3x(float c[4],
                                       const unsigned ah[4], const unsigned al[4],
                                       const unsigned bh[2], const unsigned bl[2]) {
    mma_bf16(c, ah, bl);
    mma_bf16(c, al, bh);
    mma_bf16(c, ah, bh);
}

// ---------------------------------------------------------------------------
// Preprocessing kernels
// ---------------------------------------------------------------------------
__global__ void rope_table_kernel() {
    int i = blockIdx.x * blockDim.x + threadIdx.x;
    if (i >= T_ * 64) return;
    int t = i >> 6, d = i & 63;
    float invf = powf(10000.0f, -(float)d / 64.0f);
    float ang = (float)t * invf;
    g_cos[i] = (float)cos((double)ang);
    g_sin[i] = (float)sin((double)ang);
}

__global__ void rope_apply_kernel() {
    int i = blockIdx.x * blockDim.x + threadIdx.x;
    const int total = B_ * H_ * T_ * 64;
    if (i >= total) return;
    int d  = i & 63;
    int t  = (i >> 6) & (T_ - 1);
    int bh = i >> 17;
    size_t base = ((size_t)bh * T_ + t) * D_;
    float c = g_cos[(t << 6) + d];
    float s = g_sin[(t << 6) + d];
    const float scale = 0.08838834764831845f;  // 1/sqrt(128)
    float q1 = g_Q[base + d], q2 = g_Q[base + d + 64];
    g_Q[base + d]      = (q1 * c - q2 * s) * scale;
    g_Q[base + d + 64] = (q2 * c + q1 * s) * scale;
    float k1 = g_K[base + d], k2 = g_K[base + d + 64];
    g_K[base + d]      = k1 * c - k2 * s;
    g_K[base + d + 64] = k2 * c + k1 * s;
}

// x -> (hi, lo) bf16 (device-resolved outputs)
__global__ void split_x_kernel(const float* __restrict__ X, int n4) {
    int i = blockIdx.x * blockDim.x + threadIdx.x;
    if (i >= n4) return;
    float4 v = ((const float4*)X)[i];
    unsigned h01, l01, h23, l23;
    split_pair(v.x, v.y, h01, l01);
    split_pair(v.z, v.w, h23, l23);
    ((uint2*)g_xh)[i] = make_uint2(h01, h23);
    ((uint2*)g_xl)[i] = make_uint2(l01, l23);
}

// W[K][N] -> Wh/Wl[N][K] (transpose + split); device-resolved outputs.
template <int WSEL>
__global__ void split_wT_kernel(const float* __restrict__ W) {
    __nv_bfloat16* __restrict__ Wh = (WSEL == 1) ? g_wah : g_wph;
    __nv_bfloat16* __restrict__ Wl = (WSEL == 1) ? g_wal : g_wpl;
    const int K = C_;
    const int N = (WSEL == 1) ? NQKV_ : C_;

    __shared__ float tile[32][33];
    int nb = blockIdx.x * 32, kb = blockIdx.y * 32;
    int tx = threadIdx.x & 31, ty = threadIdx.x >> 5;
#pragma unroll
    for (int r = 0; r < 32; r += 8)
        tile[ty + r][tx] = W[(size_t)(kb + ty + r) * N + nb + tx];
    __syncthreads();
#pragma unroll
    for (int r = 0; r < 32; r += 8) {
        float v = tile[tx][ty + r];
        __nv_bfloat16 h = __float2bfloat16_rn(v);
        __nv_bfloat16 l = __float2bfloat16_rn(v - __bfloat162float(h));
        size_t o = (size_t)(nb + ty + r) * K + kb + tx;
        Wh[o] = h; Wl[o] = l;
    }
}

// ---------------------------------------------------------------------------
// bf16x3 GEMM — r16 WINNER verbatim: BK=64, all cp.async, 2-stage, 1 CTA/SM,
// fragment double-buffering in the compute block.
// ---------------------------------------------------------------------------
#define GBM 128
#define GBN 128
#define GBK 64
#define GST 72
#define GTILE (128 * GST)
#define STAGE_H (4 * GTILE)
#define GEMM_SMEM_BYTES (2 * STAGE_H * 2)   // 147456
#define NKT 32

__device__ __forceinline__ void store_qkv(int r, int c, float val) {
    int b = r >> 11, t = r & 2047;
    int sec = c >> 11, cc = c & 2047;
    int h = cc >> 7, d = cc & 127;
    size_t dst = (((size_t)(b * H_ + h)) * T_ + t) * D_ + d;
    if (sec == 0)      g_Q[dst] = val;
    else if (sec == 1) g_K[dst] = val;
    else               g_V[dst] = val;
}

template <int MODE>
__global__ void __launch_bounds__(256) gemm_bf16x3_kernel(float* __restrict__ Cout) {
    extern __shared__ __align__(16) __nv_bfloat16 smg[];
    const uint32_t sbase = smem_u32(smg);

    const __nv_bfloat16* __restrict__ Ah_g = (MODE == 1) ? g_xh  : g_Yh;
    const __nv_bfloat16* __restrict__ Al_g = (MODE == 1) ? g_xl  : g_Yl;
    const __nv_bfloat16* __restrict__ Bh_g = (MODE == 1) ? g_wah : g_wph;
    const __nv_bfloat16* __restrict__ Bl_g = (MODE == 1) ? g_wal : g_wpl;

    const int tid = threadIdx.x;
    const int lane = tid & 31, warp = tid >> 5;
    const int warpM = warp >> 1, warpN = warp & 1;
    const int gid = lane >> 2, t4 = lane & 3;
    const int bm = blockIdx.y * GBM, bn = blockIdx.x * GBN;

    float acc[2][8][4];
#pragma unroll
    for (int mi = 0; mi < 2; mi++)
#pragma unroll
        for (int ni = 0; ni < 8; ni++)
#pragma unroll
            for (int q = 0; q < 4; q++) acc[mi][ni][q] = 0.f;

#define ISSUE_STAGE(s, kt) do {                                                   \
    const int kof = (kt) * GBK;                                                   \
    _Pragma("unroll")                                                             \
    for (int i = 0; i < 4; i++) {                                                 \
        int v = tid + i * 256;                                                    \
        int row = v >> 3, kc = (v & 7) * 8;                                       \
        uint32_t dbase = sbase + (uint32_t)((s) * STAGE_H + row * GST + kc) * 2;  \
        size_t srcA = (size_t)(bm + row) * 2048 + kof + kc;                       \
        size_t srcB = (size_t)(bn + row) * 2048 + kof + kc;                       \
        CP_ASYNC16(dbase + 0u * (GTILE * 2), Ah_g + srcA);                        \
        CP_ASYNC16(dbase + 1u * (GTILE * 2), Al_g + srcA);                        \
        CP_ASYNC16(dbase + 2u * (GTILE * 2), Bh_g + srcB);                        \
        CP_ASYNC16(dbase + 3u * (GTILE * 2), Bl_g + srcB);                        \
    }                                                                             \
    CP_COMMIT();                                                                  \
} while (0)

    ISSUE_STAGE(0, 0);
    ISSUE_STAGE(1, 1);

    for (int kt = 0; kt < NKT; kt++) {
        const int cur = kt & 1;
        if (kt < NKT - 2) { CP_WAIT1(); } else { CP_WAIT0(); }
        __syncthreads();

        {
            const __nv_bfloat16* Ah = smg + cur * STAGE_H;
            const __nv_bfloat16* Al = Ah + GTILE;
            const __nv_bfloat16* Bh = Al + GTILE;
            const __nv_bfloat16* Bl = Bh + GTILE;

            unsigned fah[2][2][4], fal[2][2][4], fbh[2][8][2], fbl[2][8][2];

#define LOAD_FRAGS(f, ksv) do {                                                   \
    int ko = (ksv) + 2 * t4;                                                      \
    _Pragma("unroll")                                                             \
    for (int mi = 0; mi < 2; mi++) {                                              \
        int r0 = warpM * 32 + mi * 16 + gid;                                      \
        fah[f][mi][0] = *(const unsigned*)&Ah[r0 * GST + ko];                     \
        fah[f][mi][1] = *(const unsigned*)&Ah[(r0 + 8) * GST + ko];               \
        fah[f][mi][2] = *(const unsigned*)&Ah[r0 * GST + ko + 8];                 \
        fah[f][mi][3] = *(const unsigned*)&Ah[(r0 + 8) * GST + ko + 8];           \
        fal[f][mi][0] = *(const unsigned*)&Al[r0 * GST + ko];                     \
        fal[f][mi][1] = *(const unsigned*)&Al[(r0 + 8) * GST + ko];               \
        fal[f][mi][2] = *(const unsigned*)&Al[r0 * GST + ko + 8];                 \
        fal[f][mi][3] = *(const unsigned*)&Al[(r0 + 8) * GST + ko + 8];           \
    }                                                                             \
    _Pragma("unroll")                                                             \
    for (int ni = 0; ni < 8; ni++) {                                              \
        int nc = warpN * 64 + ni * 8 + gid;                                       \
        fbh[f][ni][0] = *(const unsigned*)&Bh[nc * GST + ko];                     \
        fbh[f][ni][1] = *(const unsigned*)&Bh[nc * GST + ko + 8];                 \
        fbl[f][ni][0] = *(const unsigned*)&Bl[nc * GST + ko];                     \
        fbl[f][ni][1] = *(const unsigned*)&Bl[nc * GST + ko + 8];                 \
    }                                                                             \
} while (0)

            LOAD_FRAGS(0, 0);
#pragma unroll
            for (int ks = 0; ks < GBK; ks += 16) {
                const int cf = (ks >> 4) & 1;
                if (ks + 16 < GBK) LOAD_FRAGS(cf ^ 1, ks + 16);
#pragma unroll
                for (int ni = 0; ni < 8; ni++)
#pragma unroll
                    for (int mi = 0; mi < 2; mi++)
                        mma_3x(acc[mi][ni], fah[cf][mi], fal[cf][mi],
                               fbh[cf][ni], fbl[cf][ni]);
            }
#undef LOAD_FRAGS
        }
        __syncthreads();
        if (kt + 2 < NKT) ISSUE_STAGE(cur, kt + 2);
    }
#undef ISSUE_STAGE

    // epilogue
#pragma unroll
    for (int mi = 0; mi < 2; mi++) {
#pragma unroll
        for (int ni = 0; ni < 8; ni++) {
            int r0 = bm + warpM * 32 + mi * 16 + gid;
            int c0 = bn + warpN * 64 + ni * 8 + t4 * 2;
            if (MODE == 1) {
                store_qkv(r0,     c0,     acc[mi][ni][0]);
                store_qkv(r0,     c0 + 1, acc[mi][ni][1]);
                store_qkv(r0 + 8, c0,     acc[mi][ni][2]);
                store_qkv(r0 + 8, c0 + 1, acc[mi][ni][3]);
            } else {
                Cout[(size_t)r0 * C_ + c0]           = acc[mi][ni][0];
                Cout[(size_t)r0 * C_ + c0 + 1]       = acc[mi][ni][1];
                Cout[(size_t)(r0 + 8) * C_ + c0]     = acc[mi][ni][2];
                Cout[(size_t)(r0 + 8) * C_ + c0 + 1] = acc[mi][ni][3];
            }
        }
    }
}

// ---------------------------------------------------------------------------
// Flash attention, causal, bf16x3 — r16 base + fragment double-buffering:
// S-loop: slice-level double buffer (Q + all-ni K frags).
// PV-loop: per-di V-fragment double buffer.
// Epilogue writes pre-split Y (bf16 hi/lo) for the proj GEMM.
// ---------------------------------------------------------------------------
#define AQS 136
#define AVS 72
#define O_QH 0
#define O_QL (O_QH + 128 * AQS)
#define O_KH (O_QL + 128 * AQS)
#define O_KL (O_KH + 64 * AQS)
#define O_VTH (O_KL + 64 * AQS)
#define O_VTL (O_VTH + 128 * AVS)
#define O_PH (O_VTL + 128 * AVS)
#define O_PL (O_PH + 128 * AVS)
#define ATT_SMEM_HALVES (O_PL + 128 * AVS)
#define ATT_SMEM_BYTES (ATT_SMEM_HALVES * 2)

__global__ void __launch_bounds__(256) attn_kernel() {
    extern __shared__ __align__(16) __nv_bfloat16 sa[];
    __nv_bfloat16* Qh  = sa + O_QH;
    __nv_bfloat16* Ql  = sa + O_QL;
    __nv_bfloat16* Kh  = sa + O_KH;
    __nv_bfloat16* Kl  = sa + O_KL;
    __nv_bfloat16* VTh = sa + O_VTH;
    __nv_bfloat16* VTl = sa + O_VTL;
    __nv_bfloat16* Ph  = sa + O_PH;
    __nv_bfloat16* Pl  = sa + O_PL;

    const int tid = threadIdx.x;
    const int lane = tid & 31, w = tid >> 5;
    const int gid = lane >> 2, t4 = lane & 3;
    const int qtile = blockIdx.x, bh = blockIdx.y;
    const int qbase = qtile * 128;

    const float* Qg = g_Q + ((size_t)bh * T_ + qbase) * D_;
    const float* Kg = g_K + (size_t)bh * T_ * D_;
    const float* Vg = g_V + (size_t)bh * T_ * D_;

#pragma unroll
    for (int i = 0; i < 16; i++) {
        int u = tid + i * 256;
        int row = u >> 5, c4 = (u & 31) << 2;
        float4 v = *(const float4*)(Qg + (size_t)row * D_ + c4);
        unsigned h01, l01, h23, l23;
        split_pair(v.x, v.y, h01, l01);
        split_pair(v.z, v.w, h23, l23);
        *(unsigned*)&Qh[row * AQS + c4]     = h01;
        *(unsigned*)&Qh[row * AQS + c4 + 2] = h23;
        *(unsigned*)&Ql[row * AQS + c4]     = l01;
        *(unsigned*)&Ql[row * AQS + c4 + 2] = l23;
    }

    float o[16][4];
#pragma unroll
    for (int a = 0; a < 16; a++)
#pragma unroll
        for (int c = 0; c < 4; c++) o[a][c] = 0.f;
    float m0 = -1e30f, m1 = -1e30f, l0 = 0.f, l1 = 0.f;

    const int mrow = w * 16;
    const int rl0 = mrow + gid, rl1 = mrow + gid + 8;
    const int njt = 2 * qtile + 2;

    for (int j = 0; j < njt; j++) {
        __syncthreads();
#pragma unroll
        for (int i = 0; i < 8; i++) {
            int u = tid + i * 256;
            int row = u >> 5, c4 = (u & 31) << 2;
            float4 kv = *(const float4*)(Kg + ((size_t)j * 64 + row) * D_ + c4);
            unsigned h01, l01, h23, l23;
            split_pair(kv.x, kv.y, h01, l01);
            split_pair(kv.z, kv.w, h23, l23);
            *(unsigned*)&Kh[row * AQS + c4]     = h01;
            *(unsigned*)&Kh[row * AQS + c4 + 2] = h23;
            *(unsigned*)&Kl[row * AQS + c4]     = l01;
            *(unsigned*)&Kl[row * AQS + c4 + 2] = l23;
        }
#pragma unroll
        for (int i = 0; i < 8; i++) {
            int u = tid + i * 256;
            int d = u & 127, k0 = (u >> 7) << 2;
            float v0 = Vg[((size_t)j * 64 + k0)     * D_ + d];
            float v1 = Vg[((size_t)j * 64 + k0 + 1) * D_ + d];
            float v2 = Vg[((size_t)j * 64 + k0 + 2) * D_ + d];
            float v3 = Vg[((size_t)j * 64 + k0 + 3) * D_ + d];
            unsigned h01, l01, h23, l23;
            split_pair(v0, v1, h01, l01);
            split_pair(v2, v3, h23, l23);
            *(unsigned*)&VTh[d * AVS + k0]     = h01;
            *(unsigned*)&VTh[d * AVS + k0 + 2] = h23;
            *(unsigned*)&VTl[d * AVS + k0]     = l01;
            *(unsigned*)&VTl[d * AVS + k0 + 2] = l23;
        }
        __syncthreads();

        // S = Q K^T (128x64), bf16x3, slice-level fragment double buffer
        float s[8][4];
#pragma unroll
        for (int ni = 0; ni < 8; ni++)
#pragma unroll
            for (int q = 0; q < 4; q++) s[ni][q] = 0.f;

        {
            unsigned qh2[2][4], ql2[2][4], kh2[2][8][2], kl2[2][8][2];
#define LOAD_SFRAGS(f, ksv) do {                                                   \
    int ko = (ksv) + 2 * t4;                                                       \
    qh2[f][0] = *(const unsigned*)&Qh[rl0 * AQS + ko];                             \
    qh2[f][1] = *(const unsigned*)&Qh[rl1 * AQS + ko];                             \
    qh2[f][2] = *(const unsigned*)&Qh[rl0 * AQS + ko + 8];                         \
    qh2[f][3] = *(const unsigned*)&Qh[rl1 * AQS + ko + 8];                         \
    ql2[f][0] = *(const unsigned*)&Ql[rl0 * AQS + ko];                             \
    ql2[f][1] = *(const unsigned*)&Ql[rl1 * AQS + ko];                             \
    ql2[f][2] = *(const unsigned*)&Ql[rl0 * AQS + ko + 8];                         \
    ql2[f][3] = *(const unsigned*)&Ql[rl1 * AQS + ko + 8];                         \
    _Pragma("unroll")                                                              \
    for (int ni = 0; ni < 8; ni++) {                                               \
        int nc = ni * 8 + gid;                                                     \
        kh2[f][ni][0] = *(const unsigned*)&Kh[nc * AQS + ko];                      \
        kh2[f][ni][1] = *(const unsigned*)&Kh[nc * AQS + ko + 8];                  \
        kl2[f][ni][0] = *(const unsigned*)&Kl[nc * AQS + ko];                      \
        kl2[f][ni][1] = *(const unsigned*)&Kl[nc * AQS + ko + 8];                  \
    }                                                                              \
} while (0)
            LOAD_SFRAGS(0, 0);
#pragma unroll
            for (int ks = 0; ks < 128; ks += 16) {
                const int cf = (ks >> 4) & 1;
                if (ks + 16 < 128) LOAD_SFRAGS(cf ^ 1, ks + 16);
#pragma unroll
                for (int ni = 0; ni < 8; ni++)
                    mma_3x(s[ni], qh2[cf], ql2[cf], kh2[cf][ni], kl2[cf][ni]);
            }
#undef LOAD_SFRAGS
        }

        if (j >= 2 * qtile) {
            const int rg0 = qbase + rl0, rg1 = qbase + rl1;
#pragma unroll
            for (int ni = 0; ni < 8; ni++) {
                int cg = j * 64 + ni * 8 + t4 * 2;
                if (cg     > rg0) s[ni][0] = -1e30f;
                if (cg + 1 > rg0) s[ni][1] = -1e30f;
                if (cg     > rg1) s[ni][2] = -1e30f;
                if (cg + 1 > rg1) s[ni][3] = -1e30f;
            }
        }

        float rmax0 = -1e30f, rmax1 = -1e30f;
#pragma unroll
        for (int ni = 0; ni < 8; ni++) {
            rmax0 = fmaxf(rmax0, fmaxf(s[ni][0], s[ni][1]));
            rmax1 = fmaxf(rmax1, fmaxf(s[ni][2], s[ni][3]));
        }
        rmax0 = fmaxf(rmax0, __shfl_xor_sync(0xffffffffu, rmax0, 1));
        rmax0 = fmaxf(rmax0, __shfl_xor_sync(0xffffffffu, rmax0, 2));
        rmax1 = fmaxf(rmax1, __shfl_xor_sync(0xffffffffu, rmax1, 1));
        rmax1 = fmaxf(rmax1, __shfl_xor_sync(0xffffffffu, rmax1, 2));

        float nm0 = fmaxf(m0, rmax0), nm1 = fmaxf(m1, rmax1);
        float a0 = __expf(m0 - nm0), a1 = __expf(m1 - nm1);
        m0 = nm0; m1 = nm1;

        float sum0 = 0.f, sum1 = 0.f;
#pragma unroll
        for (int ni = 0; ni < 8; ni++) {
            s[ni][0] = __expf(s[ni][0] - nm0);
            s[ni][1] = __expf(s[ni][1] - nm0);
            s[ni][2] = __expf(s[ni][2] - nm1);
            s[ni][3] = __expf(s[ni][3] - nm1);
            sum0 += s[ni][0] + s[ni][1];
            sum1 += s[ni][2] + s[ni][3];
        }
        sum0 += __shfl_xor_sync(0xffffffffu, sum0, 1);
        sum0 += __shfl_xor_sync(0xffffffffu, sum0, 2);
        sum1 += __shfl_xor_sync(0xffffffffu, sum1, 1);
        sum1 += __shfl_xor_sync(0xffffffffu, sum1, 2);
        l0 = l0 * a0 + sum0;
        l1 = l1 * a1 + sum1;

#pragma unroll
        for (int di = 0; di < 16; di++) {
            o[di][0] *= a0; o[di][1] *= a0;
            o[di][2] *= a1; o[di][3] *= a1;
        }

#pragma unroll
        for (int ni = 0; ni < 8; ni++) {
            int cc = ni * 8 + 2 * t4;
            unsigned h01, lo01, h23, lo23;
            split_pair(s[ni][0], s[ni][1], h01, lo01);
            split_pair(s[ni][2], s[ni][3], h23, lo23);
            *(unsigned*)&Ph[rl0 * AVS + cc] = h01;
            *(unsigned*)&Pl[rl0 * AVS + cc] = lo01;
            *(unsigned*)&Ph[rl1 * AVS + cc] = h23;
            *(unsigned*)&Pl[rl1 * AVS + cc] = lo23;
        }
        __syncwarp();

        // O += P @ V (bf16x3), per-di V-fragment double buffer
#pragma unroll
        for (int kk = 0; kk < 64; kk += 16) {
            int ko = kk + 2 * t4;
            unsigned pah[4], pal[4];
            pah[0] = *(const unsigned*)&Ph[rl0 * AVS + ko];
            pah[1] = *(const unsigned*)&Ph[rl1 * AVS + ko];
            pah[2] = *(const unsigned*)&Ph[rl0 * AVS + ko + 8];
            pah[3] = *(const unsigned*)&Ph[rl1 * AVS + ko + 8];
            pal[0] = *(const unsigned*)&Pl[rl0 * AVS + ko];
            pal[1] = *(const unsigned*)&Pl[rl1 * AVS + ko];
            pal[2] = *(const unsigned*)&Pl[rl0 * AVS + ko + 8];
            pal[3] = *(const unsigned*)&Pl[rl1 * AVS + ko + 8];

            unsigned vh2[2][2], vl2[2][2];
            {
                int nc = gid;  // di = 0
                vh2[0][0] = *(const unsigned*)&VTh[nc * AVS + ko];
                vh2[0][1] = *(const unsigned*)&VTh[nc * AVS + ko + 8];
                vl2[0][0] = *(const unsigned*)&VTl[nc * AVS + ko];
                vl2[0][1] = *(const unsigned*)&VTl[nc * AVS + ko + 8];
            }
#pragma unroll
            for (int di = 0; di < 16; di++) {
                const int cf = di & 1;
                if (di + 1 < 16) {
                    int nc = (di + 1) * 8 + gid;
                    vh2[cf ^ 1][0] = *(const unsigned*)&VTh[nc * AVS + ko];
                    vh2[cf ^ 1][1] = *(const unsigned*)&VTh[nc * AVS + ko + 8];
                    vl2[cf ^ 1][0] = *(const unsigned*)&VTl[nc * AVS + ko];
                    vl2[cf ^ 1][1] = *(const unsigned*)&VTl[nc * AVS + ko + 8];
                }
                mma_3x(o[di], pah, pal, vh2[cf], vl2[cf]);
            }
        }
        __syncwarp();
    }

    // Normalize + write pre-split Y (bf16 hi/lo) for the proj GEMM
    float il0 = 1.0f / l0, il1 = 1.0f / l1;
    int b = bh >> 4, h = bh & 15;
    int rg0 = qbase + rl0, rg1 = qbase + rl1;
#pragma unroll
    for (int di = 0; di < 16; di++) {
        size_t base0 = ((size_t)b * T_ + rg0) * C_ + h * D_ + di * 8 + t4 * 2;
        size_t base1 = ((size_t)b * T_ + rg1) * C_ + h * D_ + di * 8 + t4 * 2;
        unsigned hh, ll;
        split_pair(o[di][0] * il0, o[di][1] * il0, hh, ll);
        *(unsigned*)&g_Yh[base0] = hh;
        *(unsigned*)&g_Yl[base0] = ll;
        split_pair(o[di][2] * il1, o[di][3] * il1, hh, ll);
        *(unsigned*)&g_Yh[base1] = hh;
        *(unsigned*)&g_Yl[base1] = ll;
    }
}

// ---------------------------------------------------------------------------
// Launch
// ---------------------------------------------------------------------------
extern "C" void kernel_launch(void* const* d_in, const int* in_sizes, int n_in,
                              void* d_out, int out_size) {
    const float* x      = (const float*)d_in[0];
    const float* w_attn = (const float*)d_in[1];
    const float* w_proj = (const float*)d_in[2];
    float* out = (float*)d_out;
    (void)in_sizes; (void)n_in; (void)out_size;

    cudaFuncSetAttribute(attn_kernel, cudaFuncAttributeMaxDynamicSharedMemorySize,
                         ATT_SMEM_BYTES);
    cudaFuncSetAttribute(gemm_bf16x3_kernel<1>,
                         cudaFuncAttributeMaxDynamicSharedMemorySize, GEMM_SMEM_BYTES);
    cudaFuncSetAttribute(gemm_bf16x3_kernel<2>,
                         cudaFuncAttributeMaxDynamicSharedMemorySize, GEMM_SMEM_BYTES);

    // preprocessing: tables + pre-split operands (device-resolved outputs)
    rope_table_kernel<<<(T_ * 64 + 255) / 256, 256>>>();
    split_x_kernel<<<(MROWS * C_ / 4 + 255) / 256, 256>>>(x, MROWS * C_ / 4);
    split_wT_kernel<1><<<dim3(NQKV_ / 32, C_ / 32), 256>>>(w_attn);
    split_wT_kernel<2><<<dim3(C_ / 32, C_ / 32), 256>>>(w_proj);

    // QKV GEMM -> g_Q/K/V ([B,H,T,D] fp32)
    gemm_bf16x3_kernel<1><<<dim3(NQKV_ / GBN, MROWS / GBM), 256, GEMM_SMEM_BYTES>>>(nullptr);

    // RoPE + scale fold
    rope_apply_kernel<<<(B_ * H_ * T_ * 64 + 255) / 256, 256>>>();

    // attention -> g_Yh/g_Yl
    attn_kernel<<<dim3(T_ / 128, B_ * H_), 256, ATT_SMEM_BYTES>>>();

    // out projection -> d_out
    gemm_bf16x3_kernel<2><<<dim3(C_ / GBN, MROWS / GBM), 256, GEMM_SMEM_BYTES>>>(out);
}